// round 11
// baseline (speedup 1.0000x reference)
#include <cuda_runtime.h>
#include <math.h>
#include <stdint.h>

// ---------------- problem constants ----------------
#define FHW    32
#define NPIX   1024          // 32*32
#define C_IN   256
#define C_MID  512
#define KTOT   2304          // 256*9
#define A_ANCH 9
#define NBOX   9216          // 1024*9
#define NW     144           // NBOX/64
#define IOU_THR 0.7f

// ---------------- static device scratch (no allocs allowed) ----------------
__device__ float g_wt[KTOT * C_MID];                 // conv1 weights transposed [k][co]
__device__ float g_col[KTOT * NPIX];                 // im2col [k][p]
__device__ float g_h[NPIX * C_MID];                  // hidden activations [p][c]
__device__ float g_boxes[NBOX * 4];
__device__ float g_scores[NBOX];
__device__ unsigned long long g_key[NBOX];
__device__ unsigned char g_valid[NBOX];
__device__ int g_rank[NBOX];
__device__ int g_order[NBOX];
__device__ float4 g_bsorted[NBOX];
__device__ unsigned long long g_mask[(size_t)NBOX * NW];
__device__ unsigned long long g_keepmask[NW];
__device__ int g_V;

// anchor widths/heights: a = size_idx*3 + ratio_idx, sizes {32,64,128}, ratios {.5,1,2}
__constant__ float c_aw[9] = {
    45.254833995939045f, 32.0f, 22.627416997969522f,
    90.50966799187809f,  64.0f, 45.254833995939045f,
    181.01933598375618f, 128.0f, 90.50966799187809f };
__constant__ float c_ah[9] = {
    22.627416997969522f, 32.0f, 45.254833995939045f,
    45.254833995939045f, 64.0f, 90.50966799187809f,
    90.50966799187809f,  128.0f, 181.01933598375618f };

// ---------------- K0: transpose conv1 weights [512][2304] -> [2304][512] ----------------
__global__ void k_transpose(const float* __restrict__ w) {
    __shared__ float tile[32][33];
    int kb = blockIdx.x * 32, cb = blockIdx.y * 32;
    for (int i = threadIdx.y; i < 32; i += 8) {
        tile[i][threadIdx.x] = w[(cb + i) * KTOT + kb + threadIdx.x];
    }
    __syncthreads();
    for (int i = threadIdx.y; i < 32; i += 8) {
        g_wt[(kb + i) * C_MID + cb + threadIdx.x] = tile[threadIdx.x][i];
    }
}

// ---------------- K1: im2col, k = c*9 + ky*3 + kx ----------------
__global__ void k_im2col(const float* __restrict__ feat) {
    int e = blockIdx.x * 256 + threadIdx.x;          // 2304*1024 elements exactly
    int k = e >> 10, p = e & 1023;
    int c = k / 9, t = k - c * 9;
    int y = (p >> 5) + t / 3 - 1;
    int x = (p & 31) + t % 3 - 1;
    float v = 0.0f;
    if ((unsigned)y < 32u && (unsigned)x < 32u) v = feat[c * NPIX + y * 32 + x];
    g_col[e] = v;
}

// ---------------- K2: SGEMM 1024x512x2304 + bias + relu ----------------
// block: 64 pixels x 64 out-channels, 256 threads, 4x4 per thread
__global__ void __launch_bounds__(256) k_gemm(const float* __restrict__ bias) {
    __shared__ float As[32][68];
    __shared__ float Bs[32][68];
    const int tx = threadIdx.x & 15;      // co group
    const int ty = threadIdx.x >> 4;      // pixel group
    const int co0 = blockIdx.x * 64;
    const int p0  = blockIdx.y * 64;

    float acc[4][4];
#pragma unroll
    for (int i = 0; i < 4; i++)
#pragma unroll
        for (int j = 0; j < 4; j++) acc[i][j] = 0.0f;

    for (int k0 = 0; k0 < KTOT; k0 += 32) {
#pragma unroll
        for (int i = 0; i < 2; i++) {
            int idx = threadIdx.x + i * 256;              // 0..511 float4 slots
            int kk = idx >> 4, q = idx & 15;
            *(float4*)&As[kk][q * 4] = *(const float4*)&g_col[(size_t)(k0 + kk) * NPIX + p0 + q * 4];
            *(float4*)&Bs[kk][q * 4] = *(const float4*)&g_wt[(size_t)(k0 + kk) * C_MID + co0 + q * 4];
        }
        __syncthreads();
#pragma unroll
        for (int kk = 0; kk < 32; kk++) {
            float4 a = *(const float4*)&As[kk][ty * 4];
            float4 b = *(const float4*)&Bs[kk][tx * 4];
            float av[4] = {a.x, a.y, a.z, a.w};
            float bv[4] = {b.x, b.y, b.z, b.w};
#pragma unroll
            for (int i = 0; i < 4; i++)
#pragma unroll
                for (int j = 0; j < 4; j++) acc[i][j] += av[i] * bv[j];
        }
        __syncthreads();
    }
#pragma unroll
    for (int i = 0; i < 4; i++) {
        int p = p0 + ty * 4 + i;
#pragma unroll
        for (int j = 0; j < 4; j++) {
            int co = co0 + tx * 4 + j;
            float v = acc[i][j] + bias[co];
            g_h[(size_t)p * C_MID + co] = fmaxf(v, 0.0f);
        }
    }
}

// ---------------- K3: heads (45 dots of 512) + decode + sort keys ----------------
__global__ void __launch_bounds__(128) k_heads(const float* __restrict__ w2, const float* __restrict__ b2,
                                               const float* __restrict__ w3, const float* __restrict__ b3) {
    __shared__ float hrow[512];
    __shared__ float res[48];
    const int p = blockIdx.x;
    const int tid = threadIdx.x, lane = tid & 31, warp = tid >> 5;

    *(float4*)&hrow[tid * 4] = *(const float4*)&g_h[(size_t)p * C_MID + tid * 4];
    __syncthreads();

    for (int o = warp; o < 45; o += 4) {
        const float* wr; float bv;
        if (o < 9) { wr = w2 + o * 512; bv = b2[o]; }
        else       { wr = w3 + (o - 9) * 512; bv = b3[o - 9]; }
        float acc = 0.0f;
#pragma unroll 4
        for (int c = lane; c < 512; c += 32) acc += hrow[c] * wr[c];
#pragma unroll
        for (int s = 16; s; s >>= 1) acc += __shfl_xor_sync(0xffffffffu, acc, s);
        if (lane == 0) res[o] = acc + bv;
    }
    __syncthreads();

    if (tid < 9) {
        const int a = tid;
        float logit = res[a];
        float score = 1.0f / (1.0f + expf(-logit));
        float o0 = res[9 + a * 4 + 0];
        float o1 = res[9 + a * 4 + 1];
        float o2 = res[9 + a * 4 + 2];
        float o3 = res[9 + a * 4 + 3];
        int y = p >> 5, x = p & 31;
        float acx = ((float)x + 0.5f) * 16.0f;
        float acy = ((float)y + 0.5f) * 16.0f;
        float aw = c_aw[a], ah = c_ah[a];
        float cx = acx + o0 * aw;
        float cy = acy + o1 * ah;
        float bw = aw * expf(o2);
        float bh = ah * expf(o3);
        float x1 = fminf(fmaxf(cx - bw * 0.5f, 0.0f), 512.0f);
        float y1 = fminf(fmaxf(cy - bh * 0.5f, 0.0f), 512.0f);
        float x2 = fminf(fmaxf(cx + bw * 0.5f, 0.0f), 512.0f);
        float y2 = fminf(fmaxf(cy + bh * 0.5f, 0.0f), 512.0f);
        bool valid = (x2 - x1 >= 0.001f) && (y2 - y1 >= 0.001f) && (score >= 0.5f);
        int i = p * 9 + a;
        g_boxes[i * 4 + 0] = x1;
        g_boxes[i * 4 + 1] = y1;
        g_boxes[i * 4 + 2] = x2;
        g_boxes[i * 4 + 3] = y2;
        g_scores[i] = score;
        g_valid[i] = valid ? 1 : 0;
        float seff = valid ? score : -INFINITY;
        unsigned int b = __float_as_uint(seff);
        unsigned int u = (b & 0x80000000u) ? ~b : (b | 0x80000000u); // ascending by seff
        unsigned int d = ~u;                                         // descending by seff
        g_key[i] = ((unsigned long long)d << 32) | (unsigned int)i;  // tie: idx ascending
    }
}

// ---------------- K3b: count valid ----------------
__global__ void k_count() {
    __shared__ int sm[1024];
    int t = threadIdx.x;
    int s = 0;
    for (int i = t; i < NBOX; i += 1024) s += g_valid[i];
    sm[t] = s;
    __syncthreads();
    for (int st = 512; st; st >>= 1) {
        if (t < st) sm[t] += sm[t + st];
        __syncthreads();
    }
    if (t == 0) g_V = sm[0];
}

// ---------------- K4a: rank count (stable sort by counting) ----------------
__global__ void __launch_bounds__(256) k_rank() {
    __shared__ unsigned long long sk[256];
    const int i = blockIdx.x * 256 + threadIdx.x;
    const unsigned long long ki = g_key[i];
    const int base = blockIdx.y * 1024;
    int cnt = 0;
    for (int t = 0; t < 4; t++) {
        sk[threadIdx.x] = g_key[base + t * 256 + threadIdx.x];
        __syncthreads();
#pragma unroll 8
        for (int j = 0; j < 256; j++) cnt += (sk[j] < ki) ? 1 : 0;
        __syncthreads();
    }
    atomicAdd(&g_rank[i], cnt);
}

// ---------------- K4b: scatter into sorted order ----------------
__global__ void k_scatter() {
    int i = blockIdx.x * 256 + threadIdx.x;
    int r = g_rank[i];
    g_order[r] = i;
    g_bsorted[r] = *(const float4*)&g_boxes[i * 4];
}

// ---------------- K5: pairwise IoU bitmask (sorted order, valid prefix only) ----------------
__global__ void __launch_bounds__(64) k_mask() {
    const int rc = blockIdx.y, cc = blockIdx.x;
    if (cc < rc) return;                 // only j > i needed
    const int V = g_V;
    if (rc * 64 >= V) return;            // uniform
    __shared__ float4 cb[64];
    cb[threadIdx.x] = g_bsorted[cc * 64 + threadIdx.x];
    __syncthreads();
    const int i = rc * 64 + threadIdx.x;
    if (i >= V) return;
    float4 bi = g_bsorted[i];
    float areai = (bi.z - bi.x) * (bi.w - bi.y);
    unsigned long long bits = 0;
    int jmax = min(64, V - cc * 64);
    for (int jj = 0; jj < jmax; jj++) {
        int j = cc * 64 + jj;
        if (j <= i) continue;
        float4 bj = cb[jj];
        float ix1 = fmaxf(bi.x, bj.x);
        float iy1 = fmaxf(bi.y, bj.y);
        float ix2 = fminf(bi.z, bj.z);
        float iy2 = fminf(bi.w, bj.w);
        float inter = fmaxf(ix2 - ix1, 0.0f) * fmaxf(iy2 - iy1, 0.0f);
        float uni = areai + (bj.z - bj.x) * (bj.w - bj.y) - inter;
        float iou = inter / fmaxf(uni, 1e-9f);
        if (iou > IOU_THR) bits |= 1ull << jj;
    }
    g_mask[(size_t)i * NW + cc] = bits;
}

// ---------------- K6: serial greedy NMS over bitmask (single block) ----------------
__global__ void __launch_bounds__(256) k_nms() {
    __shared__ unsigned long long supp[NW];
    __shared__ unsigned long long keepm[NW];
    __shared__ unsigned long long roww[64];
    __shared__ unsigned long long curkeep;
    const int t = threadIdx.x;
    for (int w = t; w < NW; w += 256) { supp[w] = 0ull; keepm[w] = 0ull; }
    const int V = g_V;
    const int NC = (V + 63) >> 6;
    __syncthreads();
    for (int c = 0; c < NC; c++) {
        int limit = min(64, V - c * 64);
        if (t < limit) roww[t] = g_mask[(size_t)(c * 64 + t) * NW + c];
        __syncthreads();
        if (t == 0) {
            unsigned long long cur = supp[c], km = 0ull;
            for (int b = 0; b < limit; b++) {
                if (!((cur >> b) & 1ull)) { km |= 1ull << b; cur |= roww[b]; }
            }
            keepm[c] = km;
            curkeep = km;
        }
        __syncthreads();
        unsigned long long km = curkeep;
        for (int w = c + 1 + t; w < NC; w += 256) {
            unsigned long long acc = 0ull, m = km;
            while (m) {
                int b = __ffsll((long long)m) - 1;
                m &= m - 1;
                acc |= g_mask[(size_t)(c * 64 + b) * NW + w];
            }
            supp[w] |= acc;
        }
        __syncthreads();
    }
    for (int w = t; w < NW; w += 256) g_keepmask[w] = keepm[w];
}

// ---------------- K7: write output (N,5): boxes*keep, score*keep ----------------
__global__ void k_out(float* __restrict__ out) {
    int p = blockIdx.x * 256 + threadIdx.x;   // sorted position, exactly 9216
    int V = g_V;
    bool keep = (p < V) && ((g_keepmask[p >> 6] >> (p & 63)) & 1ull);
    int orig = g_order[p];
    float4 b = *(const float4*)&g_boxes[orig * 4];
    float s = g_scores[orig];
    float k = keep ? 1.0f : 0.0f;
    out[orig * 5 + 0] = b.x * k;
    out[orig * 5 + 1] = b.y * k;
    out[orig * 5 + 2] = b.z * k;
    out[orig * 5 + 3] = b.w * k;
    out[orig * 5 + 4] = s * k;
}

// ---------------- host launcher ----------------
extern "C" void kernel_launch(void* const* d_in, const int* in_sizes, int n_in,
                              void* d_out, int out_size) {
    const float* feat = (const float*)d_in[0];
    const float* w1   = (const float*)d_in[1];
    const float* b1   = (const float*)d_in[2];
    const float* w2   = (const float*)d_in[3];
    const float* b2   = (const float*)d_in[4];
    const float* w3   = (const float*)d_in[5];
    const float* b3   = (const float*)d_in[6];
    float* out = (float*)d_out;

    void* rankptr = nullptr;
    cudaGetSymbolAddress(&rankptr, g_rank);
    cudaMemsetAsync(rankptr, 0, NBOX * sizeof(int), 0);

    k_transpose<<<dim3(KTOT / 32, C_MID / 32), dim3(32, 8)>>>(w1);
    k_im2col<<<(KTOT * NPIX) / 256, 256>>>(feat);
    k_gemm<<<dim3(C_MID / 64, NPIX / 64), 256>>>(b1);
    k_heads<<<NPIX, 128>>>(w2, b2, w3, b3);
    k_count<<<1, 1024>>>();
    k_rank<<<dim3(NBOX / 256, 9), 256>>>();
    k_scatter<<<NBOX / 256, 256>>>();
    k_mask<<<dim3(NW, NW), 64>>>();
    k_nms<<<1, 256>>>();
    k_out<<<NBOX / 256, 256>>>(out);
}

// round 12
// speedup vs baseline: 2.3152x; 2.3152x over previous
#include <cuda_runtime.h>
#include <math.h>
#include <stdint.h>

// ---------------- problem constants ----------------
#define FHW    32
#define NPIX   1024          // 32*32
#define C_IN   256
#define C_MID  512
#define KTOT   2304          // 256*9
#define A_ANCH 9
#define NBOX   9216          // 1024*9
#define NW     144           // NBOX/64
#define IOU_THR 0.7f

// ---------------- static device scratch (no allocs allowed) ----------------
__device__ float g_wt[KTOT * C_MID];                 // conv1 weights transposed [k][co]
__device__ float g_col[KTOT * NPIX];                 // im2col [k][p]
__device__ float g_h[NPIX * C_MID];                  // hidden activations [p][c]
__device__ float g_boxes[NBOX * 4];
__device__ float g_scores[NBOX];
__device__ unsigned long long g_key[NBOX];
__device__ unsigned char g_valid[NBOX];
__device__ int g_rank[NBOX];
__device__ int g_order[NBOX];
__device__ float4 g_bsorted[NBOX];
__device__ unsigned long long g_mask[(size_t)NBOX * NW];
__device__ unsigned long long g_keepmask[NW];
__device__ int g_V;

// anchor widths/heights: a = size_idx*3 + ratio_idx, sizes {32,64,128}, ratios {.5,1,2}
__constant__ float c_aw[9] = {
    45.254833995939045f, 32.0f, 22.627416997969522f,
    90.50966799187809f,  64.0f, 45.254833995939045f,
    181.01933598375618f, 128.0f, 90.50966799187809f };
__constant__ float c_ah[9] = {
    22.627416997969522f, 32.0f, 45.254833995939045f,
    45.254833995939045f, 64.0f, 90.50966799187809f,
    90.50966799187809f,  128.0f, 181.01933598375618f };

// ---------------- K0: transpose conv1 weights [512][2304] -> [2304][512] ----------------
__global__ void k_transpose(const float* __restrict__ w) {
    __shared__ float tile[32][33];
    int kb = blockIdx.x * 32, cb = blockIdx.y * 32;
    for (int i = threadIdx.y; i < 32; i += 8) {
        tile[i][threadIdx.x] = w[(cb + i) * KTOT + kb + threadIdx.x];
    }
    __syncthreads();
    for (int i = threadIdx.y; i < 32; i += 8) {
        g_wt[(kb + i) * C_MID + cb + threadIdx.x] = tile[threadIdx.x][i];
    }
}

// ---------------- K1: im2col, k = c*9 + ky*3 + kx ----------------
__global__ void k_im2col(const float* __restrict__ feat) {
    int e = blockIdx.x * 256 + threadIdx.x;          // 2304*1024 elements exactly
    int k = e >> 10, p = e & 1023;
    int c = k / 9, t = k - c * 9;
    int y = (p >> 5) + t / 3 - 1;
    int x = (p & 31) + t % 3 - 1;
    float v = 0.0f;
    if ((unsigned)y < 32u && (unsigned)x < 32u) v = feat[c * NPIX + y * 32 + x];
    g_col[e] = v;
}

// ---------------- K2: SGEMM 1024x512x2304 + bias + relu ----------------
// block: 64 pixels x 64 out-channels, 256 threads, 4x4 per thread
__global__ void __launch_bounds__(256) k_gemm(const float* __restrict__ bias) {
    __shared__ float As[32][68];
    __shared__ float Bs[32][68];
    const int tx = threadIdx.x & 15;      // co group
    const int ty = threadIdx.x >> 4;      // pixel group
    const int co0 = blockIdx.x * 64;
    const int p0  = blockIdx.y * 64;

    float acc[4][4];
#pragma unroll
    for (int i = 0; i < 4; i++)
#pragma unroll
        for (int j = 0; j < 4; j++) acc[i][j] = 0.0f;

    for (int k0 = 0; k0 < KTOT; k0 += 32) {
#pragma unroll
        for (int i = 0; i < 2; i++) {
            int idx = threadIdx.x + i * 256;              // 0..511 float4 slots
            int kk = idx >> 4, q = idx & 15;
            *(float4*)&As[kk][q * 4] = *(const float4*)&g_col[(size_t)(k0 + kk) * NPIX + p0 + q * 4];
            *(float4*)&Bs[kk][q * 4] = *(const float4*)&g_wt[(size_t)(k0 + kk) * C_MID + co0 + q * 4];
        }
        __syncthreads();
#pragma unroll
        for (int kk = 0; kk < 32; kk++) {
            float4 a = *(const float4*)&As[kk][ty * 4];
            float4 b = *(const float4*)&Bs[kk][tx * 4];
            float av[4] = {a.x, a.y, a.z, a.w};
            float bv[4] = {b.x, b.y, b.z, b.w};
#pragma unroll
            for (int i = 0; i < 4; i++)
#pragma unroll
                for (int j = 0; j < 4; j++) acc[i][j] += av[i] * bv[j];
        }
        __syncthreads();
    }
#pragma unroll
    for (int i = 0; i < 4; i++) {
        int p = p0 + ty * 4 + i;
#pragma unroll
        for (int j = 0; j < 4; j++) {
            int co = co0 + tx * 4 + j;
            float v = acc[i][j] + bias[co];
            g_h[(size_t)p * C_MID + co] = fmaxf(v, 0.0f);
        }
    }
}

// ---------------- K3: heads (45 dots of 512) + decode + sort keys ----------------
__global__ void __launch_bounds__(128) k_heads(const float* __restrict__ w2, const float* __restrict__ b2,
                                               const float* __restrict__ w3, const float* __restrict__ b3) {
    __shared__ float hrow[512];
    __shared__ float res[48];
    const int p = blockIdx.x;
    const int tid = threadIdx.x, lane = tid & 31, warp = tid >> 5;

    *(float4*)&hrow[tid * 4] = *(const float4*)&g_h[(size_t)p * C_MID + tid * 4];
    __syncthreads();

    for (int o = warp; o < 45; o += 4) {
        const float* wr; float bv;
        if (o < 9) { wr = w2 + o * 512; bv = b2[o]; }
        else       { wr = w3 + (o - 9) * 512; bv = b3[o - 9]; }
        float acc = 0.0f;
#pragma unroll 4
        for (int c = lane; c < 512; c += 32) acc += hrow[c] * wr[c];
#pragma unroll
        for (int s = 16; s; s >>= 1) acc += __shfl_xor_sync(0xffffffffu, acc, s);
        if (lane == 0) res[o] = acc + bv;
    }
    __syncthreads();

    if (tid < 9) {
        const int a = tid;
        float logit = res[a];
        float score = 1.0f / (1.0f + expf(-logit));
        float o0 = res[9 + a * 4 + 0];
        float o1 = res[9 + a * 4 + 1];
        float o2 = res[9 + a * 4 + 2];
        float o3 = res[9 + a * 4 + 3];
        int y = p >> 5, x = p & 31;
        float acx = ((float)x + 0.5f) * 16.0f;
        float acy = ((float)y + 0.5f) * 16.0f;
        float aw = c_aw[a], ah = c_ah[a];
        float cx = acx + o0 * aw;
        float cy = acy + o1 * ah;
        float bw = aw * expf(o2);
        float bh = ah * expf(o3);
        float x1 = fminf(fmaxf(cx - bw * 0.5f, 0.0f), 512.0f);
        float y1 = fminf(fmaxf(cy - bh * 0.5f, 0.0f), 512.0f);
        float x2 = fminf(fmaxf(cx + bw * 0.5f, 0.0f), 512.0f);
        float y2 = fminf(fmaxf(cy + bh * 0.5f, 0.0f), 512.0f);
        bool valid = (x2 - x1 >= 0.001f) && (y2 - y1 >= 0.001f) && (score >= 0.5f);
        int i = p * 9 + a;
        g_boxes[i * 4 + 0] = x1;
        g_boxes[i * 4 + 1] = y1;
        g_boxes[i * 4 + 2] = x2;
        g_boxes[i * 4 + 3] = y2;
        g_scores[i] = score;
        g_valid[i] = valid ? 1 : 0;
        float seff = valid ? score : -INFINITY;
        unsigned int b = __float_as_uint(seff);
        unsigned int u = (b & 0x80000000u) ? ~b : (b | 0x80000000u); // ascending by seff
        unsigned int d = ~u;                                         // descending by seff
        g_key[i] = ((unsigned long long)d << 32) | (unsigned int)i;  // tie: idx ascending
    }
}

// ---------------- K3b: count valid ----------------
__global__ void k_count() {
    __shared__ int sm[1024];
    int t = threadIdx.x;
    int s = 0;
    for (int i = t; i < NBOX; i += 1024) s += g_valid[i];
    sm[t] = s;
    __syncthreads();
    for (int st = 512; st; st >>= 1) {
        if (t < st) sm[t] += sm[t + st];
        __syncthreads();
    }
    if (t == 0) g_V = sm[0];
}

// ---------------- K4a: rank count (stable sort by counting) ----------------
__global__ void __launch_bounds__(256) k_rank() {
    __shared__ unsigned long long sk[256];
    const int i = blockIdx.x * 256 + threadIdx.x;
    const unsigned long long ki = g_key[i];
    const int base = blockIdx.y * 1024;
    int cnt = 0;
    for (int t = 0; t < 4; t++) {
        sk[threadIdx.x] = g_key[base + t * 256 + threadIdx.x];
        __syncthreads();
#pragma unroll 8
        for (int j = 0; j < 256; j++) cnt += (sk[j] < ki) ? 1 : 0;
        __syncthreads();
    }
    atomicAdd(&g_rank[i], cnt);
}

// ---------------- K4b: scatter into sorted order ----------------
__global__ void k_scatter() {
    int i = blockIdx.x * 256 + threadIdx.x;
    int r = g_rank[i];
    g_order[r] = i;
    g_bsorted[r] = *(const float4*)&g_boxes[i * 4];
}

// ---------------- K5: pairwise IoU bitmask (sorted order, valid prefix only) ----------------
__global__ void __launch_bounds__(64) k_mask() {
    const int rc = blockIdx.y, cc = blockIdx.x;
    if (cc < rc) return;                 // only j > i needed
    const int V = g_V;
    if (rc * 64 >= V) return;            // uniform
    __shared__ float4 cb[64];
    cb[threadIdx.x] = g_bsorted[cc * 64 + threadIdx.x];
    __syncthreads();
    const int i = rc * 64 + threadIdx.x;
    if (i >= V) return;
    float4 bi = g_bsorted[i];
    float areai = (bi.z - bi.x) * (bi.w - bi.y);
    unsigned long long bits = 0;
    int jmax = min(64, V - cc * 64);
    for (int jj = 0; jj < jmax; jj++) {
        int j = cc * 64 + jj;
        if (j <= i) continue;
        float4 bj = cb[jj];
        float ix1 = fmaxf(bi.x, bj.x);
        float iy1 = fmaxf(bi.y, bj.y);
        float ix2 = fminf(bi.z, bj.z);
        float iy2 = fminf(bi.w, bj.w);
        float inter = fmaxf(ix2 - ix1, 0.0f) * fmaxf(iy2 - iy1, 0.0f);
        float uni = areai + (bj.z - bj.x) * (bj.w - bj.y) - inter;
        float iou = inter / fmaxf(uni, 1e-9f);
        if (iou > IOU_THR) bits |= 1ull << jj;
    }
    g_mask[(size_t)i * NW + cc] = bits;
}

// ---------------- K6: serial greedy NMS over bitmask (single block) ----------------
// Cross-chunk suppression rewritten: fixed-trip fully-unrolled 64-row loop per
// target word, predicated on warp-uniform keep-mask bits. All live loads are
// independent (MLP ~30-40) and coalesced across lanes (consecutive w).
__global__ void __launch_bounds__(256) k_nms() {
    __shared__ unsigned long long supp[NW];
    __shared__ unsigned long long keepm[NW];
    __shared__ unsigned long long roww[64];
    __shared__ unsigned long long s_km;
    const int t = threadIdx.x;
    for (int w = t; w < NW; w += 256) { supp[w] = 0ull; keepm[w] = 0ull; }
    const int V = g_V;
    const int NC = (V + 63) >> 6;
    __syncthreads();
    for (int c = 0; c < NC; c++) {
        const int limit = min(64, V - c * 64);
        if (t < 64) roww[t] = (t < limit) ? g_mask[(size_t)(c * 64 + t) * NW + c] : 0ull;
        __syncthreads();
        if (t == 0) {
            unsigned long long cur = supp[c], km = 0ull;
            for (int b = 0; b < limit; b++) {
                if (!((cur >> b) & 1ull)) { km |= 1ull << b; cur |= roww[b]; }
            }
            keepm[c] = km;
            s_km = km;
        }
        __syncthreads();
        const unsigned long long km = s_km;
        const unsigned long long* rowbase = &g_mask[(size_t)(c * 64) * NW];
        for (int w = c + 1 + t; w < NC; w += 256) {
            unsigned long long acc = 0ull;
#pragma unroll
            for (int b = 0; b < 64; b++) {
                if ((km >> b) & 1ull) acc |= rowbase[(size_t)b * NW + w];
            }
            supp[w] |= acc;
        }
        __syncthreads();
    }
    for (int w = t; w < NW; w += 256) g_keepmask[w] = keepm[w];
}

// ---------------- K7: write output (N,5): boxes*keep, score*keep ----------------
__global__ void k_out(float* __restrict__ out) {
    int p = blockIdx.x * 256 + threadIdx.x;   // sorted position, exactly 9216
    int V = g_V;
    bool keep = (p < V) && ((g_keepmask[p >> 6] >> (p & 63)) & 1ull);
    int orig = g_order[p];
    float4 b = *(const float4*)&g_boxes[orig * 4];
    float s = g_scores[orig];
    float k = keep ? 1.0f : 0.0f;
    out[orig * 5 + 0] = b.x * k;
    out[orig * 5 + 1] = b.y * k;
    out[orig * 5 + 2] = b.z * k;
    out[orig * 5 + 3] = b.w * k;
    out[orig * 5 + 4] = s * k;
}

// ---------------- host launcher ----------------
extern "C" void kernel_launch(void* const* d_in, const int* in_sizes, int n_in,
                              void* d_out, int out_size) {
    const float* feat = (const float*)d_in[0];
    const float* w1   = (const float*)d_in[1];
    const float* b1   = (const float*)d_in[2];
    const float* w2   = (const float*)d_in[3];
    const float* b2   = (const float*)d_in[4];
    const float* w3   = (const float*)d_in[5];
    const float* b3   = (const float*)d_in[6];
    float* out = (float*)d_out;

    void* rankptr = nullptr;
    cudaGetSymbolAddress(&rankptr, g_rank);
    cudaMemsetAsync(rankptr, 0, NBOX * sizeof(int), 0);

    k_transpose<<<dim3(KTOT / 32, C_MID / 32), dim3(32, 8)>>>(w1);
    k_im2col<<<(KTOT * NPIX) / 256, 256>>>(feat);
    k_gemm<<<dim3(C_MID / 64, NPIX / 64), 256>>>(b1);
    k_heads<<<NPIX, 128>>>(w2, b2, w3, b3);
    k_count<<<1, 1024>>>();
    k_rank<<<dim3(NBOX / 256, 9), 256>>>();
    k_scatter<<<NBOX / 256, 256>>>();
    k_mask<<<dim3(NW, NW), 64>>>();
    k_nms<<<1, 256>>>();
    k_out<<<NBOX / 256, 256>>>(out);
}

// round 13
// speedup vs baseline: 2.5412x; 1.0976x over previous
#include <cuda_runtime.h>
#include <math.h>
#include <stdint.h>

// ---------------- problem constants ----------------
#define FHW    32
#define NPIX   1024          // 32*32
#define C_IN   256
#define C_MID  512
#define KTOT   2304          // 256*9
#define KSPLIT 4
#define KPER   (KTOT / KSPLIT)   // 576
#define A_ANCH 9
#define NBOX   9216          // 1024*9
#define NW     144           // NBOX/64
#define IOU_THR 0.7f

// ---------------- static device scratch (no allocs allowed) ----------------
__device__ float g_wt[KTOT * C_MID];                 // conv1 weights transposed [k][co]
__device__ float g_col[KTOT * NPIX];                 // im2col [k][p]
__device__ float g_hp[KSPLIT * NPIX * C_MID];        // split-K partial activations
__device__ float g_boxes[NBOX * 4];
__device__ float g_scores[NBOX];
__device__ unsigned long long g_key[NBOX];
__device__ unsigned char g_valid[NBOX];
__device__ int g_rank[NBOX];
__device__ int g_order[NBOX];
__device__ float4 g_bsorted[NBOX];
__device__ unsigned long long g_mask[(size_t)NBOX * NW];
__device__ unsigned long long g_keepmask[NW];
__device__ int g_V;

// anchor widths/heights: a = size_idx*3 + ratio_idx, sizes {32,64,128}, ratios {.5,1,2}
__constant__ float c_aw[9] = {
    45.254833995939045f, 32.0f, 22.627416997969522f,
    90.50966799187809f,  64.0f, 45.254833995939045f,
    181.01933598375618f, 128.0f, 90.50966799187809f };
__constant__ float c_ah[9] = {
    22.627416997969522f, 32.0f, 45.254833995939045f,
    45.254833995939045f, 64.0f, 90.50966799187809f,
    90.50966799187809f,  128.0f, 181.01933598375618f };

// ---------------- packed f32x2 helpers (sm_103a) ----------------
__device__ __forceinline__ void ffma2(unsigned long long& acc, unsigned long long a, unsigned long long b) {
    asm("fma.rn.f32x2 %0, %1, %2, %0;" : "+l"(acc) : "l"(a), "l"(b));
}
__device__ __forceinline__ unsigned long long dup2(float x) {
    unsigned long long r;
    asm("mov.b64 %0, {%1, %1};" : "=l"(r) : "f"(x));
    return r;
}
__device__ __forceinline__ void unpack2(unsigned long long v, float& lo, float& hi) {
    asm("mov.b64 {%0, %1}, %2;" : "=f"(lo), "=f"(hi) : "l"(v));
}

// ---------------- K0: transpose conv1 weights [512][2304] -> [2304][512] ----------------
__global__ void k_transpose(const float* __restrict__ w) {
    __shared__ float tile[32][33];
    int kb = blockIdx.x * 32, cb = blockIdx.y * 32;
    for (int i = threadIdx.y; i < 32; i += 8) {
        tile[i][threadIdx.x] = w[(cb + i) * KTOT + kb + threadIdx.x];
    }
    __syncthreads();
    for (int i = threadIdx.y; i < 32; i += 8) {
        g_wt[(kb + i) * C_MID + cb + threadIdx.x] = tile[threadIdx.x][i];
    }
}

// ---------------- K1: im2col, k = c*9 + ky*3 + kx ----------------
__global__ void k_im2col(const float* __restrict__ feat) {
    int e = blockIdx.x * 256 + threadIdx.x;          // 2304*1024 elements exactly
    int k = e >> 10, p = e & 1023;
    int c = k / 9, t = k - c * 9;
    int y = (p >> 5) + t / 3 - 1;
    int x = (p & 31) + t % 3 - 1;
    float v = 0.0f;
    if ((unsigned)y < 32u && (unsigned)x < 32u) v = feat[c * NPIX + y * 32 + x];
    g_col[e] = v;
}

// ---------------- K2: SGEMM 1024x512x2304, split-K x4, f32x2 packed FMA ----------------
// tile: 128 pixels x 128 out-channels, 256 threads, 8x8 per thread.
// Accumulators packed as f32x2 along the co dimension (4 pairs per row).
__global__ void __launch_bounds__(256) k_gemm() {
    __shared__ float As[32][128];
    __shared__ float Bs[32][128];
    const int tx = threadIdx.x & 15;      // co group (8 co each)
    const int ty = threadIdx.x >> 4;      // pixel group (8 p each)
    const int co0 = blockIdx.x * 128;     // 4 co tiles
    const int p0  = blockIdx.y * 128;     // 8 p tiles
    const int kz  = blockIdx.z;           // split-K index

    unsigned long long acc[8][4];
#pragma unroll
    for (int i = 0; i < 8; i++)
#pragma unroll
        for (int j = 0; j < 4; j++) acc[i][j] = 0ull;

    const int kbeg = kz * KPER;
    for (int k0 = kbeg; k0 < kbeg + KPER; k0 += 32) {
#pragma unroll
        for (int i = 0; i < 4; i++) {
            int idx = threadIdx.x + i * 256;          // 0..1023 float4 slots
            int kk = idx >> 5, q = idx & 31;
            *(float4*)&As[kk][q * 4] = *(const float4*)&g_col[(size_t)(k0 + kk) * NPIX + p0 + q * 4];
            *(float4*)&Bs[kk][q * 4] = *(const float4*)&g_wt[(size_t)(k0 + kk) * C_MID + co0 + q * 4];
        }
        __syncthreads();
#pragma unroll
        for (int kk = 0; kk < 32; kk++) {
            float4 a0 = *(const float4*)&As[kk][ty * 8];
            float4 a1 = *(const float4*)&As[kk][ty * 8 + 4];
            ulonglong2 bq = *(const ulonglong2*)&Bs[kk][tx * 8];       // co pairs 0,1
            ulonglong2 br = *(const ulonglong2*)&Bs[kk][tx * 8 + 4];   // co pairs 2,3
            float av[8] = {a0.x, a0.y, a0.z, a0.w, a1.x, a1.y, a1.z, a1.w};
#pragma unroll
            for (int i = 0; i < 8; i++) {
                unsigned long long ai = dup2(av[i]);
                ffma2(acc[i][0], ai, bq.x);
                ffma2(acc[i][1], ai, bq.y);
                ffma2(acc[i][2], ai, br.x);
                ffma2(acc[i][3], ai, br.y);
            }
        }
        __syncthreads();
    }
    float* outb = &g_hp[(size_t)kz * NPIX * C_MID];
#pragma unroll
    for (int i = 0; i < 8; i++) {
        int p = p0 + ty * 8 + i;
        float v[8];
#pragma unroll
        for (int j = 0; j < 4; j++) unpack2(acc[i][j], v[2 * j], v[2 * j + 1]);
        float* dst = &outb[(size_t)p * C_MID + co0 + tx * 8];
        *(float4*)dst       = make_float4(v[0], v[1], v[2], v[3]);
        *(float4*)(dst + 4) = make_float4(v[4], v[5], v[6], v[7]);
    }
}

// ---------------- K3: combine partials + bias + relu, heads, decode, sort keys ----------------
__global__ void __launch_bounds__(128) k_heads(const float* __restrict__ b1,
                                               const float* __restrict__ w2, const float* __restrict__ b2,
                                               const float* __restrict__ w3, const float* __restrict__ b3) {
    __shared__ float hrow[512];
    __shared__ float res[48];
    const int p = blockIdx.x;
    const int tid = threadIdx.x, lane = tid & 31, warp = tid >> 5;

    {
        size_t off = (size_t)p * C_MID + tid * 4;
        float4 s0 = *(const float4*)&g_hp[off];
        float4 s1 = *(const float4*)&g_hp[(size_t)1 * NPIX * C_MID + off];
        float4 s2 = *(const float4*)&g_hp[(size_t)2 * NPIX * C_MID + off];
        float4 s3 = *(const float4*)&g_hp[(size_t)3 * NPIX * C_MID + off];
        float4 bb = *(const float4*)&b1[tid * 4];
        float4 h;
        h.x = fmaxf(s0.x + s1.x + s2.x + s3.x + bb.x, 0.0f);
        h.y = fmaxf(s0.y + s1.y + s2.y + s3.y + bb.y, 0.0f);
        h.z = fmaxf(s0.z + s1.z + s2.z + s3.z + bb.z, 0.0f);
        h.w = fmaxf(s0.w + s1.w + s2.w + s3.w + bb.w, 0.0f);
        *(float4*)&hrow[tid * 4] = h;
    }
    __syncthreads();

    for (int o = warp; o < 45; o += 4) {
        const float* wr; float bv;
        if (o < 9) { wr = w2 + o * 512; bv = b2[o]; }
        else       { wr = w3 + (o - 9) * 512; bv = b3[o - 9]; }
        float acc = 0.0f;
#pragma unroll 4
        for (int c = lane; c < 512; c += 32) acc += hrow[c] * wr[c];
#pragma unroll
        for (int s = 16; s; s >>= 1) acc += __shfl_xor_sync(0xffffffffu, acc, s);
        if (lane == 0) res[o] = acc + bv;
    }
    __syncthreads();

    if (tid < 9) {
        const int a = tid;
        float logit = res[a];
        float score = 1.0f / (1.0f + expf(-logit));
        float o0 = res[9 + a * 4 + 0];
        float o1 = res[9 + a * 4 + 1];
        float o2 = res[9 + a * 4 + 2];
        float o3 = res[9 + a * 4 + 3];
        int y = p >> 5, x = p & 31;
        float acx = ((float)x + 0.5f) * 16.0f;
        float acy = ((float)y + 0.5f) * 16.0f;
        float aw = c_aw[a], ah = c_ah[a];
        float cx = acx + o0 * aw;
        float cy = acy + o1 * ah;
        float bw = aw * expf(o2);
        float bh = ah * expf(o3);
        float x1 = fminf(fmaxf(cx - bw * 0.5f, 0.0f), 512.0f);
        float y1 = fminf(fmaxf(cy - bh * 0.5f, 0.0f), 512.0f);
        float x2 = fminf(fmaxf(cx + bw * 0.5f, 0.0f), 512.0f);
        float y2 = fminf(fmaxf(cy + bh * 0.5f, 0.0f), 512.0f);
        bool valid = (x2 - x1 >= 0.001f) && (y2 - y1 >= 0.001f) && (score >= 0.5f);
        int i = p * 9 + a;
        g_boxes[i * 4 + 0] = x1;
        g_boxes[i * 4 + 1] = y1;
        g_boxes[i * 4 + 2] = x2;
        g_boxes[i * 4 + 3] = y2;
        g_scores[i] = score;
        g_valid[i] = valid ? 1 : 0;
        float seff = valid ? score : -INFINITY;
        unsigned int b = __float_as_uint(seff);
        unsigned int u = (b & 0x80000000u) ? ~b : (b | 0x80000000u); // ascending by seff
        unsigned int d = ~u;                                         // descending by seff
        g_key[i] = ((unsigned long long)d << 32) | (unsigned int)i;  // tie: idx ascending
    }
}

// ---------------- K3b: count valid ----------------
__global__ void k_count() {
    __shared__ int sm[1024];
    int t = threadIdx.x;
    int s = 0;
    for (int i = t; i < NBOX; i += 1024) s += g_valid[i];
    sm[t] = s;
    __syncthreads();
    for (int st = 512; st; st >>= 1) {
        if (t < st) sm[t] += sm[t + st];
        __syncthreads();
    }
    if (t == 0) g_V = sm[0];
}

// ---------------- K4a: rank count (stable sort by counting) ----------------
__global__ void __launch_bounds__(256) k_rank() {
    __shared__ unsigned long long sk[256];
    const int i = blockIdx.x * 256 + threadIdx.x;
    const unsigned long long ki = g_key[i];
    const int base = blockIdx.y * 1024;
    int cnt = 0;
    for (int t = 0; t < 4; t++) {
        sk[threadIdx.x] = g_key[base + t * 256 + threadIdx.x];
        __syncthreads();
#pragma unroll 8
        for (int j = 0; j < 256; j++) cnt += (sk[j] < ki) ? 1 : 0;
        __syncthreads();
    }
    atomicAdd(&g_rank[i], cnt);
}

// ---------------- K4b: scatter into sorted order ----------------
__global__ void k_scatter() {
    int i = blockIdx.x * 256 + threadIdx.x;
    int r = g_rank[i];
    g_order[r] = i;
    g_bsorted[r] = *(const float4*)&g_boxes[i * 4];
}

// ---------------- K5: pairwise IoU bitmask (sorted order, valid prefix only) ----------------
__global__ void __launch_bounds__(64) k_mask() {
    const int rc = blockIdx.y, cc = blockIdx.x;
    if (cc < rc) return;                 // only j > i needed
    const int V = g_V;
    if (rc * 64 >= V) return;            // uniform
    __shared__ float4 cb[64];
    cb[threadIdx.x] = g_bsorted[cc * 64 + threadIdx.x];
    __syncthreads();
    const int i = rc * 64 + threadIdx.x;
    if (i >= V) return;
    float4 bi = g_bsorted[i];
    float areai = (bi.z - bi.x) * (bi.w - bi.y);
    unsigned long long bits = 0;
    int jmax = min(64, V - cc * 64);
    for (int jj = 0; jj < jmax; jj++) {
        int j = cc * 64 + jj;
        if (j <= i) continue;
        float4 bj = cb[jj];
        float ix1 = fmaxf(bi.x, bj.x);
        float iy1 = fmaxf(bi.y, bj.y);
        float ix2 = fminf(bi.z, bj.z);
        float iy2 = fminf(bi.w, bj.w);
        float inter = fmaxf(ix2 - ix1, 0.0f) * fmaxf(iy2 - iy1, 0.0f);
        float uni = areai + (bj.z - bj.x) * (bj.w - bj.y) - inter;
        float iou = inter / fmaxf(uni, 1e-9f);
        if (iou > IOU_THR) bits |= 1ull << jj;
    }
    g_mask[(size_t)i * NW + cc] = bits;
}

// ---------------- K6: serial greedy NMS over bitmask (single block) ----------------
// Diag rows double-buffered in shared (prefetched by warp 1 during cross-OR);
// t0 scan is hoisted LDS + pure-ALU select/or chain; cross-chunk OR is the
// fixed-trip fully-unrolled predicated-load loop from R11.
__global__ void __launch_bounds__(256) k_nms() {
    __shared__ unsigned long long supp[NW];
    __shared__ unsigned long long keepm[NW];
    __shared__ unsigned long long dbuf[2][64];
    __shared__ unsigned long long s_km;
    const int t = threadIdx.x;
    for (int w = t; w < NW; w += 256) { supp[w] = 0ull; keepm[w] = 0ull; }
    const int V = g_V;
    const int NC = (V + 63) >> 6;
    if (t < 64) dbuf[0][t] = (t < V) ? g_mask[(size_t)t * NW + 0] : 0ull;
    __syncthreads();
    for (int c = 0; c < NC; c++) {
        if (t == 0) {
            const unsigned long long* rb = dbuf[c & 1];
            unsigned long long cur = supp[c], km = 0ull;
#pragma unroll
            for (int b = 0; b < 64; b++) {
                bool keep = !((cur >> b) & 1ull);
                km |= keep ? (1ull << b) : 0ull;
                cur |= keep ? rb[b] : 0ull;
            }
            keepm[c] = km;
            s_km = km;
        }
        __syncthreads();
        const unsigned long long km = s_km;
        // prefetch next chunk's diag rows (warp 1)
        if (t >= 64 && t < 128) {
            int b = t - 64, nc1 = c + 1;
            if (nc1 < NC) {
                int row = nc1 * 64 + b;
                dbuf[nc1 & 1][b] = (row < V) ? g_mask[(size_t)row * NW + nc1] : 0ull;
            }
        }
        const unsigned long long* rowbase = &g_mask[(size_t)(c * 64) * NW];
        for (int w = c + 1 + t; w < NC; w += 256) {
            unsigned long long acc = 0ull;
#pragma unroll
            for (int b = 0; b < 64; b++) {
                if ((km >> b) & 1ull) acc |= rowbase[(size_t)b * NW + w];
            }
            supp[w] |= acc;
        }
        __syncthreads();
    }
    for (int w = t; w < NW; w += 256) g_keepmask[w] = keepm[w];
}

// ---------------- K7: write output (N,5): boxes*keep, score*keep ----------------
__global__ void k_out(float* __restrict__ out) {
    int p = blockIdx.x * 256 + threadIdx.x;   // sorted position, exactly 9216
    int V = g_V;
    bool keep = (p < V) && ((g_keepmask[p >> 6] >> (p & 63)) & 1ull);
    int orig = g_order[p];
    float4 b = *(const float4*)&g_boxes[orig * 4];
    float s = g_scores[orig];
    float k = keep ? 1.0f : 0.0f;
    out[orig * 5 + 0] = b.x * k;
    out[orig * 5 + 1] = b.y * k;
    out[orig * 5 + 2] = b.z * k;
    out[orig * 5 + 3] = b.w * k;
    out[orig * 5 + 4] = s * k;
}

// ---------------- host launcher ----------------
extern "C" void kernel_launch(void* const* d_in, const int* in_sizes, int n_in,
                              void* d_out, int out_size) {
    const float* feat = (const float*)d_in[0];
    const float* w1   = (const float*)d_in[1];
    const float* b1   = (const float*)d_in[2];
    const float* w2   = (const float*)d_in[3];
    const float* b2   = (const float*)d_in[4];
    const float* w3   = (const float*)d_in[5];
    const float* b3   = (const float*)d_in[6];
    float* out = (float*)d_out;

    void* rankptr = nullptr;
    cudaGetSymbolAddress(&rankptr, g_rank);
    cudaMemsetAsync(rankptr, 0, NBOX * sizeof(int), 0);

    k_transpose<<<dim3(KTOT / 32, C_MID / 32), dim3(32, 8)>>>(w1);
    k_im2col<<<(KTOT * NPIX) / 256, 256>>>(feat);
    k_gemm<<<dim3(C_MID / 128, NPIX / 128, KSPLIT), 256>>>();
    k_heads<<<NPIX, 128>>>(b1, w2, b2, w3, b3);
    k_count<<<1, 1024>>>();
    k_rank<<<dim3(NBOX / 256, 9), 256>>>();
    k_scatter<<<NBOX / 256, 256>>>();
    k_mask<<<dim3(NW, NW), 64>>>();
    k_nms<<<1, 256>>>();
    k_out<<<NBOX / 256, 256>>>(out);
}

// round 14
// speedup vs baseline: 2.8022x; 1.1027x over previous
#include <cuda_runtime.h>
#include <math.h>
#include <stdint.h>

// ---------------- problem constants ----------------
#define FHW    32
#define NPIX   1024          // 32*32
#define C_IN   256
#define C_MID  512
#define KTOT   2304          // 256*9
#define KSPLIT 4
#define KPER   (KTOT / KSPLIT)   // 576
#define A_ANCH 9
#define NBOX   9216          // 1024*9
#define NW     144           // NBOX/64
#define IOU_THR 0.7f

// ---------------- static device scratch (no allocs allowed) ----------------
__device__ float g_wt[KTOT * C_MID];                 // conv1 weights transposed [k][co]
__device__ float g_col[KTOT * NPIX];                 // im2col [k][p]
__device__ float g_hp[KSPLIT * NPIX * C_MID];        // split-K partial activations
__device__ float g_boxes[NBOX * 4];
__device__ float g_scores[NBOX];
__device__ __align__(16) unsigned long long g_key[NBOX];
__device__ unsigned char g_valid[NBOX];
__device__ int g_rank[NBOX];
__device__ int g_order[NBOX];
__device__ float4 g_bsorted[NBOX];
__device__ unsigned long long g_mask[(size_t)NBOX * NW];
__device__ unsigned long long g_keepmask[NW];
__device__ int g_V;

// anchor widths/heights: a = size_idx*3 + ratio_idx, sizes {32,64,128}, ratios {.5,1,2}
__constant__ float c_aw[9] = {
    45.254833995939045f, 32.0f, 22.627416997969522f,
    90.50966799187809f,  64.0f, 45.254833995939045f,
    181.01933598375618f, 128.0f, 90.50966799187809f };
__constant__ float c_ah[9] = {
    22.627416997969522f, 32.0f, 45.254833995939045f,
    45.254833995939045f, 64.0f, 90.50966799187809f,
    90.50966799187809f,  128.0f, 181.01933598375618f };

// ---------------- packed f32x2 helpers (sm_103a) ----------------
__device__ __forceinline__ void ffma2(unsigned long long& acc, unsigned long long a, unsigned long long b) {
    asm("fma.rn.f32x2 %0, %1, %2, %0;" : "+l"(acc) : "l"(a), "l"(b));
}
__device__ __forceinline__ unsigned long long dup2(float x) {
    unsigned long long r;
    asm("mov.b64 %0, {%1, %1};" : "=l"(r) : "f"(x));
    return r;
}
__device__ __forceinline__ void unpack2(unsigned long long v, float& lo, float& hi) {
    asm("mov.b64 {%0, %1}, %2;" : "=f"(lo), "=f"(hi) : "l"(v));
}

// ---------------- K0: transpose conv1 weights [512][2304] -> [2304][512] ----------------
// (launched twice with kb0 = 0 / 1152 so that k_gemm lands as the 5th launch -> ncu target)
__global__ void k_transpose(const float* __restrict__ w, int kb0) {
    __shared__ float tile[32][33];
    int kb = kb0 + blockIdx.x * 32, cb = blockIdx.y * 32;
    for (int i = threadIdx.y; i < 32; i += 8) {
        tile[i][threadIdx.x] = w[(cb + i) * KTOT + kb + threadIdx.x];
    }
    __syncthreads();
    for (int i = threadIdx.y; i < 32; i += 8) {
        g_wt[(kb + i) * C_MID + cb + threadIdx.x] = tile[threadIdx.x][i];
    }
}

// ---------------- K1: im2col, k = c*9 + ky*3 + kx ----------------
__global__ void k_im2col(const float* __restrict__ feat) {
    int e = blockIdx.x * 256 + threadIdx.x;          // 2304*1024 elements exactly
    int k = e >> 10, p = e & 1023;
    int c = k / 9, t = k - c * 9;
    int y = (p >> 5) + t / 3 - 1;
    int x = (p & 31) + t % 3 - 1;
    float v = 0.0f;
    if ((unsigned)y < 32u && (unsigned)x < 32u) v = feat[c * NPIX + y * 32 + x];
    g_col[e] = v;
}

// ---------------- K2: SGEMM 1024x512x2304, split-K x4, f32x2 packed FMA ----------------
// tile: 128 pixels x 128 out-channels, 256 threads, 8x8 per thread.
__global__ void __launch_bounds__(256) k_gemm() {
    __shared__ float As[32][128];
    __shared__ float Bs[32][128];
    const int tx = threadIdx.x & 15;      // co group (8 co each)
    const int ty = threadIdx.x >> 4;      // pixel group (8 p each)
    const int co0 = blockIdx.x * 128;     // 4 co tiles
    const int p0  = blockIdx.y * 128;     // 8 p tiles
    const int kz  = blockIdx.z;           // split-K index

    unsigned long long acc[8][4];
#pragma unroll
    for (int i = 0; i < 8; i++)
#pragma unroll
        for (int j = 0; j < 4; j++) acc[i][j] = 0ull;

    const int kbeg = kz * KPER;
    for (int k0 = kbeg; k0 < kbeg + KPER; k0 += 32) {
#pragma unroll
        for (int i = 0; i < 4; i++) {
            int idx = threadIdx.x + i * 256;          // 0..1023 float4 slots
            int kk = idx >> 5, q = idx & 31;
            *(float4*)&As[kk][q * 4] = *(const float4*)&g_col[(size_t)(k0 + kk) * NPIX + p0 + q * 4];
            *(float4*)&Bs[kk][q * 4] = *(const float4*)&g_wt[(size_t)(k0 + kk) * C_MID + co0 + q * 4];
        }
        __syncthreads();
#pragma unroll
        for (int kk = 0; kk < 32; kk++) {
            float4 a0 = *(const float4*)&As[kk][ty * 8];
            float4 a1 = *(const float4*)&As[kk][ty * 8 + 4];
            ulonglong2 bq = *(const ulonglong2*)&Bs[kk][tx * 8];       // co pairs 0,1
            ulonglong2 br = *(const ulonglong2*)&Bs[kk][tx * 8 + 4];   // co pairs 2,3
            float av[8] = {a0.x, a0.y, a0.z, a0.w, a1.x, a1.y, a1.z, a1.w};
#pragma unroll
            for (int i = 0; i < 8; i++) {
                unsigned long long ai = dup2(av[i]);
                ffma2(acc[i][0], ai, bq.x);
                ffma2(acc[i][1], ai, bq.y);
                ffma2(acc[i][2], ai, br.x);
                ffma2(acc[i][3], ai, br.y);
            }
        }
        __syncthreads();
    }
    float* outb = &g_hp[(size_t)kz * NPIX * C_MID];
#pragma unroll
    for (int i = 0; i < 8; i++) {
        int p = p0 + ty * 8 + i;
        float v[8];
#pragma unroll
        for (int j = 0; j < 4; j++) unpack2(acc[i][j], v[2 * j], v[2 * j + 1]);
        float* dst = &outb[(size_t)p * C_MID + co0 + tx * 8];
        *(float4*)dst       = make_float4(v[0], v[1], v[2], v[3]);
        *(float4*)(dst + 4) = make_float4(v[4], v[5], v[6], v[7]);
    }
}

// ---------------- K3: combine partials + bias + relu, heads, decode, sort keys ----------------
__global__ void __launch_bounds__(128) k_heads(const float* __restrict__ b1,
                                               const float* __restrict__ w2, const float* __restrict__ b2,
                                               const float* __restrict__ w3, const float* __restrict__ b3) {
    __shared__ float hrow[512];
    __shared__ float res[48];
    const int p = blockIdx.x;
    const int tid = threadIdx.x, lane = tid & 31, warp = tid >> 5;

    {
        size_t off = (size_t)p * C_MID + tid * 4;
        float4 s0 = *(const float4*)&g_hp[off];
        float4 s1 = *(const float4*)&g_hp[(size_t)1 * NPIX * C_MID + off];
        float4 s2 = *(const float4*)&g_hp[(size_t)2 * NPIX * C_MID + off];
        float4 s3 = *(const float4*)&g_hp[(size_t)3 * NPIX * C_MID + off];
        float4 bb = *(const float4*)&b1[tid * 4];
        float4 h;
        h.x = fmaxf(s0.x + s1.x + s2.x + s3.x + bb.x, 0.0f);
        h.y = fmaxf(s0.y + s1.y + s2.y + s3.y + bb.y, 0.0f);
        h.z = fmaxf(s0.z + s1.z + s2.z + s3.z + bb.z, 0.0f);
        h.w = fmaxf(s0.w + s1.w + s2.w + s3.w + bb.w, 0.0f);
        *(float4*)&hrow[tid * 4] = h;
    }
    __syncthreads();

    for (int o = warp; o < 45; o += 4) {
        const float* wr; float bv;
        if (o < 9) { wr = w2 + o * 512; bv = b2[o]; }
        else       { wr = w3 + (o - 9) * 512; bv = b3[o - 9]; }
        float acc = 0.0f;
#pragma unroll 4
        for (int c = lane; c < 512; c += 32) acc += hrow[c] * wr[c];
#pragma unroll
        for (int s = 16; s; s >>= 1) acc += __shfl_xor_sync(0xffffffffu, acc, s);
        if (lane == 0) res[o] = acc + bv;
    }
    __syncthreads();

    if (tid < 9) {
        const int a = tid;
        float logit = res[a];
        float score = 1.0f / (1.0f + expf(-logit));
        float o0 = res[9 + a * 4 + 0];
        float o1 = res[9 + a * 4 + 1];
        float o2 = res[9 + a * 4 + 2];
        float o3 = res[9 + a * 4 + 3];
        int y = p >> 5, x = p & 31;
        float acx = ((float)x + 0.5f) * 16.0f;
        float acy = ((float)y + 0.5f) * 16.0f;
        float aw = c_aw[a], ah = c_ah[a];
        float cx = acx + o0 * aw;
        float cy = acy + o1 * ah;
        float bw = aw * expf(o2);
        float bh = ah * expf(o3);
        float x1 = fminf(fmaxf(cx - bw * 0.5f, 0.0f), 512.0f);
        float y1 = fminf(fmaxf(cy - bh * 0.5f, 0.0f), 512.0f);
        float x2 = fminf(fmaxf(cx + bw * 0.5f, 0.0f), 512.0f);
        float y2 = fminf(fmaxf(cy + bh * 0.5f, 0.0f), 512.0f);
        bool valid = (x2 - x1 >= 0.001f) && (y2 - y1 >= 0.001f) && (score >= 0.5f);
        int i = p * 9 + a;
        g_boxes[i * 4 + 0] = x1;
        g_boxes[i * 4 + 1] = y1;
        g_boxes[i * 4 + 2] = x2;
        g_boxes[i * 4 + 3] = y2;
        g_scores[i] = score;
        g_valid[i] = valid ? 1 : 0;
        float seff = valid ? score : -INFINITY;
        unsigned int b = __float_as_uint(seff);
        unsigned int u = (b & 0x80000000u) ? ~b : (b | 0x80000000u); // ascending by seff
        unsigned int d = ~u;                                         // descending by seff
        g_key[i] = ((unsigned long long)d << 32) | (unsigned int)i;  // tie: idx ascending
    }
}

// ---------------- K3b: count valid ----------------
__global__ void k_count() {
    __shared__ int sm[1024];
    int t = threadIdx.x;
    int s = 0;
    for (int i = t; i < NBOX; i += 1024) s += g_valid[i];
    sm[t] = s;
    __syncthreads();
    for (int st = 512; st; st >>= 1) {
        if (t < st) sm[t] += sm[t + st];
        __syncthreads();
    }
    if (t == 0) g_V = sm[0];
}

// ---------------- K4a: rank count (stable sort by counting), LDS.128 vectorized ----------------
__global__ void __launch_bounds__(256) k_rank() {
    __shared__ ulonglong2 sk[128];
    const int i = blockIdx.x * 256 + threadIdx.x;
    const unsigned long long ki = g_key[i];
    const int base = blockIdx.y * 1024;
    int cnt = 0;
    for (int t = 0; t < 4; t++) {
        if (threadIdx.x < 128)
            sk[threadIdx.x] = ((const ulonglong2*)&g_key[base + t * 256])[threadIdx.x];
        __syncthreads();
#pragma unroll 8
        for (int j = 0; j < 128; j++) {
            ulonglong2 v = sk[j];
            cnt += (v.x < ki) ? 1 : 0;
            cnt += (v.y < ki) ? 1 : 0;
        }
        __syncthreads();
    }
    atomicAdd(&g_rank[i], cnt);
}

// ---------------- K4b: scatter into sorted order ----------------
__global__ void k_scatter() {
    int i = blockIdx.x * 256 + threadIdx.x;
    int r = g_rank[i];
    g_order[r] = i;
    g_bsorted[r] = *(const float4*)&g_boxes[i * 4];
}

// ---------------- K5: pairwise IoU bitmask (sorted order, valid prefix only) ----------------
__global__ void __launch_bounds__(64) k_mask() {
    const int rc = blockIdx.y, cc = blockIdx.x;
    if (cc < rc) return;                 // only j > i needed
    const int V = g_V;
    if (rc * 64 >= V) return;            // uniform
    __shared__ float4 cb[64];
    cb[threadIdx.x] = g_bsorted[cc * 64 + threadIdx.x];
    __syncthreads();
    const int i = rc * 64 + threadIdx.x;
    if (i >= V) return;
    float4 bi = g_bsorted[i];
    float areai = (bi.z - bi.x) * (bi.w - bi.y);
    unsigned long long bits = 0;
    int jmax = min(64, V - cc * 64);
    for (int jj = 0; jj < jmax; jj++) {
        int j = cc * 64 + jj;
        float4 bj = cb[jj];
        float ix1 = fmaxf(bi.x, bj.x);
        float iy1 = fmaxf(bi.y, bj.y);
        float ix2 = fminf(bi.z, bj.z);
        float iy2 = fminf(bi.w, bj.w);
        float inter = fmaxf(ix2 - ix1, 0.0f) * fmaxf(iy2 - iy1, 0.0f);
        float uni = areai + (bj.z - bj.x) * (bj.w - bj.y) - inter;
        float iou = inter / fmaxf(uni, 1e-9f);
        unsigned long long hit = (iou > IOU_THR && j > i) ? 1ull : 0ull;
        bits |= hit << jj;
    }
    g_mask[(size_t)i * NW + cc] = bits;
}

// ---------------- K6: serial greedy NMS over bitmask (single block) ----------------
// Cross-chunk OR is now fully branch-free: 64 unconditional, unrolled,
// independent loads ANDed with an arithmetic mask derived from the keep bit.
__global__ void __launch_bounds__(256) k_nms() {
    __shared__ unsigned long long supp[NW];
    __shared__ unsigned long long keepm[NW];
    __shared__ unsigned long long dbuf[2][64];
    __shared__ unsigned long long s_km;
    const int t = threadIdx.x;
    for (int w = t; w < NW; w += 256) { supp[w] = 0ull; keepm[w] = 0ull; }
    const int V = g_V;
    const int NC = (V + 63) >> 6;
    if (t < 64) dbuf[0][t] = (t < V) ? g_mask[(size_t)t * NW + 0] : 0ull;
    __syncthreads();
    for (int c = 0; c < NC; c++) {
        if (t == 0) {
            const unsigned long long* rb = dbuf[c & 1];
            unsigned long long cur = supp[c], km = 0ull;
#pragma unroll
            for (int b = 0; b < 64; b++) {
                unsigned long long keep = (~cur >> b) & 1ull;
                km |= keep << b;
                cur |= rb[b] & (0ull - keep);
            }
            keepm[c] = km;
            s_km = km;
        }
        __syncthreads();
        const unsigned long long km = s_km;
        // prefetch next chunk's diag rows (warp 1)
        if (t >= 64 && t < 128) {
            int b = t - 64, nc1 = c + 1;
            if (nc1 < NC) {
                int row = nc1 * 64 + b;
                dbuf[nc1 & 1][b] = (row < V) ? g_mask[(size_t)row * NW + nc1] : 0ull;
            }
        }
        const unsigned long long* rowbase = &g_mask[(size_t)(c * 64) * NW];
        for (int w = c + 1 + t; w < NC; w += 256) {
            unsigned long long acc = 0ull;
#pragma unroll
            for (int b = 0; b < 64; b++) {
                unsigned long long m = 0ull - ((km >> b) & 1ull);
                acc |= rowbase[(size_t)b * NW + w] & m;
            }
            supp[w] |= acc;
        }
        __syncthreads();
    }
    for (int w = t; w < NW; w += 256) g_keepmask[w] = keepm[w];
}

// ---------------- K7: write output (N,5): boxes*keep, score*keep ----------------
__global__ void k_out(float* __restrict__ out) {
    int p = blockIdx.x * 256 + threadIdx.x;   // sorted position, exactly 9216
    int V = g_V;
    bool keep = (p < V) && ((g_keepmask[p >> 6] >> (p & 63)) & 1ull);
    int orig = g_order[p];
    float4 b = *(const float4*)&g_boxes[orig * 4];
    float s = g_scores[orig];
    float k = keep ? 1.0f : 0.0f;
    out[orig * 5 + 0] = b.x * k;
    out[orig * 5 + 1] = b.y * k;
    out[orig * 5 + 2] = b.z * k;
    out[orig * 5 + 3] = b.w * k;
    out[orig * 5 + 4] = s * k;
}

// ---------------- host launcher ----------------
extern "C" void kernel_launch(void* const* d_in, const int* in_sizes, int n_in,
                              void* d_out, int out_size) {
    const float* feat = (const float*)d_in[0];
    const float* w1   = (const float*)d_in[1];
    const float* b1   = (const float*)d_in[2];
    const float* w2   = (const float*)d_in[3];
    const float* b2   = (const float*)d_in[4];
    const float* w3   = (const float*)d_in[5];
    const float* b3   = (const float*)d_in[6];
    float* out = (float*)d_out;

    void* rankptr = nullptr;
    cudaGetSymbolAddress(&rankptr, g_rank);
    cudaMemsetAsync(rankptr, 0, NBOX * sizeof(int), 0);

    // launch order chosen so k_gemm is the 5th launch -> ncu (-s 5) captures it
    k_transpose<<<dim3(36, C_MID / 32), dim3(32, 8)>>>(w1, 0);
    k_transpose<<<dim3(36, C_MID / 32), dim3(32, 8)>>>(w1, 1152);
    k_im2col<<<(KTOT * NPIX) / 256, 256>>>(feat);
    k_gemm<<<dim3(C_MID / 128, NPIX / 128, KSPLIT), 256>>>();
    k_heads<<<NPIX, 128>>>(b1, w2, b2, w3, b3);
    k_count<<<1, 1024>>>();
    k_rank<<<dim3(NBOX / 256, 9), 256>>>();
    k_scatter<<<NBOX / 256, 256>>>();
    k_mask<<<dim3(NW, NW), 64>>>();
    k_nms<<<1, 256>>>();
    k_out<<<NBOX / 256, 256>>>(out);
}

// round 15
// speedup vs baseline: 2.8873x; 1.0304x over previous
#include <cuda_runtime.h>
#include <math.h>
#include <stdint.h>

// ---------------- problem constants ----------------
#define FHW    32
#define NPIX   1024          // 32*32
#define C_IN   256
#define C_MID  512
#define KTOT   2304          // 256*9
#define KSPLIT 9
#define KPER   (KTOT / KSPLIT)   // 256
#define A_ANCH 9
#define NBOX   9216          // 1024*9
#define NW     144           // NBOX/64
#define IOU_THR 0.7f

// ---------------- static device scratch (no allocs allowed) ----------------
__device__ float g_wt[KTOT * C_MID];                 // conv1 weights transposed [k][co]
__device__ float g_col[KTOT * NPIX];                 // im2col [k][p]
__device__ float g_hp[KSPLIT * NPIX * C_MID];        // split-K partial activations
__device__ float g_boxes[NBOX * 4];
__device__ float g_scores[NBOX];
__device__ __align__(16) unsigned long long g_key[NBOX];
__device__ int g_rank[NBOX];
__device__ int g_arr[NBOX];
__device__ int g_order[NBOX];
__device__ float4 g_bsorted[NBOX];
__device__ unsigned long long g_mask[(size_t)NBOX * NW];
__device__ unsigned long long g_keepmask[NW];
__device__ int g_V;

// anchor widths/heights: a = size_idx*3 + ratio_idx, sizes {32,64,128}, ratios {.5,1,2}
__constant__ float c_aw[9] = {
    45.254833995939045f, 32.0f, 22.627416997969522f,
    90.50966799187809f,  64.0f, 45.254833995939045f,
    181.01933598375618f, 128.0f, 90.50966799187809f };
__constant__ float c_ah[9] = {
    22.627416997969522f, 32.0f, 45.254833995939045f,
    45.254833995939045f, 64.0f, 90.50966799187809f,
    90.50966799187809f,  128.0f, 181.01933598375618f };

// ---------------- packed f32x2 helpers (sm_103a) ----------------
__device__ __forceinline__ void ffma2(unsigned long long& acc, unsigned long long a, unsigned long long b) {
    asm("fma.rn.f32x2 %0, %1, %2, %0;" : "+l"(acc) : "l"(a), "l"(b));
}
__device__ __forceinline__ unsigned long long dup2(float x) {
    unsigned long long r;
    asm("mov.b64 %0, {%1, %1};" : "=l"(r) : "f"(x));
    return r;
}
__device__ __forceinline__ void unpack2(unsigned long long v, float& lo, float& hi) {
    asm("mov.b64 {%0, %1}, %2;" : "=f"(lo), "=f"(hi) : "l"(v));
}

// ---------------- K0: fused prep: weight transpose + im2col + zero scratch ----------------
#define TBLK 1152                    // transpose blocks: (2304/32)*(512/32)
__global__ void __launch_bounds__(256) k_prep(const float* __restrict__ w, const float* __restrict__ feat) {
    const int bid = blockIdx.x;
    const int t = threadIdx.x;
    if (bid < TBLK) {                           // transpose w1 [512][2304] -> g_wt [2304][512]
        __shared__ float tile[32][33];
        int kb = (bid % 72) * 32, cb = (bid / 72) * 32;
        int tx = t & 31, ty = t >> 5;           // 32 x 8
        for (int i = ty; i < 32; i += 8)
            tile[i][tx] = w[(cb + i) * KTOT + kb + tx];
        __syncthreads();
        for (int i = ty; i < 32; i += 8)
            g_wt[(kb + i) * C_MID + cb + tx] = tile[tx][i];
    } else if (bid < TBLK + 9216) {             // im2col
        int e = (bid - TBLK) * 256 + t;         // 2304*1024 elements exactly
        int k = e >> 10, p = e & 1023;
        int c = k / 9, tt = k - c * 9;
        int y = (p >> 5) + tt / 3 - 1;
        int x = (p & 31) + tt % 3 - 1;
        float v = 0.0f;
        if ((unsigned)y < 32u && (unsigned)x < 32u) v = feat[c * NPIX + y * 32 + x];
        g_col[e] = v;
    } else {                                    // zero g_rank / g_arr / g_V
        for (int i = t; i < NBOX; i += 256) { g_rank[i] = 0; g_arr[i] = 0; }
        if (t == 0) g_V = 0;
    }
}

// ---------------- K2: SGEMM 1024x512x2304, split-K x9, f32x2, 16px x 8co micro ----------------
// tile: 256 pixels x 128 out-channels, 256 threads; FMA-bound (LDS 192 < FMA 256 cyc/kk)
__global__ void __launch_bounds__(256, 1) k_gemm() {
    __shared__ float As[32][256];   // 32 KB
    __shared__ float Bs[32][128];   // 16 KB
    const int tx = threadIdx.x & 15;      // co group (8 co each)
    const int ty = threadIdx.x >> 4;      // pixel group (16 px each)
    const int co0 = blockIdx.x * 128;     // 4 co tiles
    const int p0  = blockIdx.y * 256;     // 4 px tiles
    const int kz  = blockIdx.z;           // split-K index (9)

    unsigned long long acc[16][4];
#pragma unroll
    for (int i = 0; i < 16; i++)
#pragma unroll
        for (int j = 0; j < 4; j++) acc[i][j] = 0ull;

    const int kbeg = kz * KPER;
    for (int k0 = kbeg; k0 < kbeg + KPER; k0 += 32) {
#pragma unroll
        for (int i = 0; i < 8; i++) {         // As: 2048 float4
            int idx = threadIdx.x + i * 256;
            int kk = idx >> 6, q = idx & 63;
            *(float4*)&As[kk][q * 4] = *(const float4*)&g_col[(size_t)(k0 + kk) * NPIX + p0 + q * 4];
        }
#pragma unroll
        for (int i = 0; i < 4; i++) {         // Bs: 1024 float4
            int idx = threadIdx.x + i * 256;
            int kk = idx >> 5, q = idx & 31;
            *(float4*)&Bs[kk][q * 4] = *(const float4*)&g_wt[(size_t)(k0 + kk) * C_MID + co0 + q * 4];
        }
        __syncthreads();
#pragma unroll
        for (int kk = 0; kk < 32; kk++) {
            float4 a0 = *(const float4*)&As[kk][ty * 16];
            float4 a1 = *(const float4*)&As[kk][ty * 16 + 4];
            float4 a2 = *(const float4*)&As[kk][ty * 16 + 8];
            float4 a3 = *(const float4*)&As[kk][ty * 16 + 12];
            ulonglong2 bq = *(const ulonglong2*)&Bs[kk][tx * 8];
            ulonglong2 br = *(const ulonglong2*)&Bs[kk][tx * 8 + 4];
            float av[16] = {a0.x, a0.y, a0.z, a0.w, a1.x, a1.y, a1.z, a1.w,
                            a2.x, a2.y, a2.z, a2.w, a3.x, a3.y, a3.z, a3.w};
#pragma unroll
            for (int i = 0; i < 16; i++) {
                unsigned long long ai = dup2(av[i]);
                ffma2(acc[i][0], ai, bq.x);
                ffma2(acc[i][1], ai, bq.y);
                ffma2(acc[i][2], ai, br.x);
                ffma2(acc[i][3], ai, br.y);
            }
        }
        __syncthreads();
    }
    float* outb = &g_hp[(size_t)kz * NPIX * C_MID];
#pragma unroll
    for (int i = 0; i < 16; i++) {
        int p = p0 + ty * 16 + i;
        float v[8];
#pragma unroll
        for (int j = 0; j < 4; j++) unpack2(acc[i][j], v[2 * j], v[2 * j + 1]);
        float* dst = &outb[(size_t)p * C_MID + co0 + tx * 8];
        *(float4*)dst       = make_float4(v[0], v[1], v[2], v[3]);
        *(float4*)(dst + 4) = make_float4(v[4], v[5], v[6], v[7]);
    }
}

// ---------------- K3: combine partials + bias + relu, heads (8 px/block), decode, keys, V count ----
__global__ void __launch_bounds__(256) k_heads(const float* __restrict__ b1,
                                               const float* __restrict__ w2, const float* __restrict__ b2,
                                               const float* __restrict__ w3, const float* __restrict__ b3) {
    __shared__ float hsm[8][512];       // 16 KB
    __shared__ float res[8][48];
    __shared__ int bcnt;
    const int p0 = blockIdx.x * 8;
    const int tid = threadIdx.x, lane = tid & 31, warp = tid >> 5;
    if (tid == 0) bcnt = 0;

    // phase 1: combine 9 split-K partials + bias, relu
    for (int e = tid; e < 8 * 128; e += 256) {
        int px = e >> 7, cq = e & 127;
        size_t off = (size_t)(p0 + px) * C_MID + cq * 4;
        float4 s = *(const float4*)&g_hp[off];
#pragma unroll
        for (int sk = 1; sk < KSPLIT; sk++) {
            float4 q = *(const float4*)&g_hp[(size_t)sk * NPIX * C_MID + off];
            s.x += q.x; s.y += q.y; s.z += q.z; s.w += q.w;
        }
        float4 bb = *(const float4*)&b1[cq * 4];
        hsm[px][cq * 4 + 0] = fmaxf(s.x + bb.x, 0.0f);
        hsm[px][cq * 4 + 1] = fmaxf(s.y + bb.y, 0.0f);
        hsm[px][cq * 4 + 2] = fmaxf(s.z + bb.z, 0.0f);
        hsm[px][cq * 4 + 3] = fmaxf(s.w + bb.w, 0.0f);
    }
    __syncthreads();

    // phase 2: 45 dots of 512 for 8 pixels; warp w handles o = w, w+8, ...
    for (int o = warp; o < 45; o += 8) {
        const float* wr; float bv;
        if (o < 9) { wr = w2 + o * 512; bv = b2[o]; }
        else       { wr = w3 + (o - 9) * 512; bv = b3[o - 9]; }
        float acc[8] = {0, 0, 0, 0, 0, 0, 0, 0};
#pragma unroll 4
        for (int c = lane; c < 512; c += 32) {
            float wv = wr[c];
#pragma unroll
            for (int px = 0; px < 8; px++) acc[px] += hsm[px][c] * wv;
        }
#pragma unroll
        for (int px = 0; px < 8; px++) {
#pragma unroll
            for (int s = 16; s; s >>= 1) acc[px] += __shfl_xor_sync(0xffffffffu, acc[px], s);
            if (lane == 0) res[px][o] = acc[px] + bv;
        }
    }
    __syncthreads();

    // phase 3: decode 8 px x 9 anchors
    if (tid < 72) {
        const int pxl = tid / 9, a = tid % 9;
        const int p = p0 + pxl;
        float logit = res[pxl][a];
        float score = 1.0f / (1.0f + expf(-logit));
        float o0 = res[pxl][9 + a * 4 + 0];
        float o1 = res[pxl][9 + a * 4 + 1];
        float o2 = res[pxl][9 + a * 4 + 2];
        float o3 = res[pxl][9 + a * 4 + 3];
        int y = p >> 5, x = p & 31;
        float acx = ((float)x + 0.5f) * 16.0f;
        float acy = ((float)y + 0.5f) * 16.0f;
        float aw = c_aw[a], ah = c_ah[a];
        float cx = acx + o0 * aw;
        float cy = acy + o1 * ah;
        float bw = aw * expf(o2);
        float bh = ah * expf(o3);
        float x1 = fminf(fmaxf(cx - bw * 0.5f, 0.0f), 512.0f);
        float y1 = fminf(fmaxf(cy - bh * 0.5f, 0.0f), 512.0f);
        float x2 = fminf(fmaxf(cx + bw * 0.5f, 0.0f), 512.0f);
        float y2 = fminf(fmaxf(cy + bh * 0.5f, 0.0f), 512.0f);
        bool valid = (x2 - x1 >= 0.001f) && (y2 - y1 >= 0.001f) && (score >= 0.5f);
        int i = p * 9 + a;
        g_boxes[i * 4 + 0] = x1;
        g_boxes[i * 4 + 1] = y1;
        g_boxes[i * 4 + 2] = x2;
        g_boxes[i * 4 + 3] = y2;
        g_scores[i] = score;
        if (valid) atomicAdd(&bcnt, 1);
        float seff = valid ? score : -INFINITY;
        unsigned int b = __float_as_uint(seff);
        unsigned int u = (b & 0x80000000u) ? ~b : (b | 0x80000000u); // ascending by seff
        unsigned int d = ~u;                                         // descending by seff
        g_key[i] = ((unsigned long long)d << 32) | (unsigned int)i;  // tie: idx ascending
    }
    __syncthreads();
    if (tid == 0 && bcnt) atomicAdd(&g_V, bcnt);
}

// ---------------- K4: rank count + fused scatter (arrival counter) ----------------
__global__ void __launch_bounds__(256) k_rank() {
    __shared__ ulonglong2 sk[128];
    const int i = blockIdx.x * 256 + threadIdx.x;
    const unsigned long long ki = g_key[i];
    const int base = blockIdx.y * 1024;
    int cnt = 0;
    for (int t = 0; t < 4; t++) {
        if (threadIdx.x < 128)
            sk[threadIdx.x] = ((const ulonglong2*)&g_key[base + t * 256])[threadIdx.x];
        __syncthreads();
#pragma unroll 8
        for (int j = 0; j < 128; j++) {
            ulonglong2 v = sk[j];
            cnt += (v.x < ki) ? 1 : 0;
            cnt += (v.y < ki) ? 1 : 0;
        }
        __syncthreads();
    }
    atomicAdd(&g_rank[i], cnt);
    __threadfence();
    int n = atomicAdd(&g_arr[i], 1);
    if (n == 8) {                                    // last arrival: rank is final
        int r = atomicAdd(&g_rank[i], 0);            // atomic read of the total
        g_order[r] = i;
        g_bsorted[r] = *(const float4*)&g_boxes[i * 4];
    }
}

// ---------------- K5: pairwise IoU bitmask; block = 64 rows x 4 words ----------------
__global__ void __launch_bounds__(256) k_mask() {
    const int rc = blockIdx.y;            // row chunk 0..143
    const int wg = blockIdx.x;            // word group 0..35
    const int V = g_V;
    if (rc * 64 >= V) return;
    if (wg * 4 + 3 < rc) return;          // whole block below diagonal
    const int wl = threadIdx.x >> 6;      // 0..3
    const int rl = threadIdx.x & 63;
    const int cc = wg * 4 + wl;
    __shared__ float4 cb[4][64];
    {
        int j = cc * 64 + rl;
        cb[wl][rl] = (cc < NW && j < NBOX) ? g_bsorted[j] : make_float4(0, 0, 0, 0);
    }
    __syncthreads();
    if (cc < rc || cc * 64 >= V) return;
    const int i = rc * 64 + rl;
    if (i >= V) return;
    float4 bi = g_bsorted[i];
    float areai = (bi.z - bi.x) * (bi.w - bi.y);
    unsigned long long bits = 0;
    int jmax = min(64, V - cc * 64);
    for (int jj = 0; jj < jmax; jj++) {
        int j = cc * 64 + jj;
        float4 bj = cb[wl][jj];
        float ix1 = fmaxf(bi.x, bj.x);
        float iy1 = fmaxf(bi.y, bj.y);
        float ix2 = fminf(bi.z, bj.z);
        float iy2 = fminf(bi.w, bj.w);
        float inter = fmaxf(ix2 - ix1, 0.0f) * fmaxf(iy2 - iy1, 0.0f);
        float uni = areai + (bj.z - bj.x) * (bj.w - bj.y) - inter;
        float iou = inter / fmaxf(uni, 1e-9f);
        unsigned long long hit = (iou > IOU_THR && j > i) ? 1ull : 0ull;
        bits |= hit << jj;
    }
    g_mask[(size_t)i * NW + cc] = bits;
}

// ---------------- K6: serial greedy NMS over bitmask (single block) ----------------
__global__ void __launch_bounds__(256) k_nms() {
    __shared__ unsigned long long supp[NW];
    __shared__ unsigned long long keepm[NW];
    __shared__ unsigned long long dbuf[2][64];
    __shared__ unsigned long long s_km;
    const int t = threadIdx.x;
    for (int w = t; w < NW; w += 256) { supp[w] = 0ull; keepm[w] = 0ull; }
    const int V = g_V;
    const int NC = (V + 63) >> 6;
    if (t < 64) dbuf[0][t] = (t < V) ? g_mask[(size_t)t * NW + 0] : 0ull;
    __syncthreads();
    for (int c = 0; c < NC; c++) {
        if (t == 0) {
            const unsigned long long* rb = dbuf[c & 1];
            unsigned long long cur = supp[c], km = 0ull;
#pragma unroll
            for (int b = 0; b < 64; b++) {
                unsigned long long keep = (~cur >> b) & 1ull;
                km |= keep << b;
                cur |= rb[b] & (0ull - keep);
            }
            keepm[c] = km;
            s_km = km;
        }
        __syncthreads();
        const unsigned long long km = s_km;
        if (t >= 64 && t < 128) {                 // prefetch next diag rows
            int b = t - 64, nc1 = c + 1;
            if (nc1 < NC) {
                int row = nc1 * 64 + b;
                dbuf[nc1 & 1][b] = (row < V) ? g_mask[(size_t)row * NW + nc1] : 0ull;
            }
        }
        const unsigned long long* rowbase = &g_mask[(size_t)(c * 64) * NW];
        for (int w = c + 1 + t; w < NC; w += 256) {
            unsigned long long acc = 0ull;
#pragma unroll
            for (int b = 0; b < 64; b++) {
                unsigned long long m = 0ull - ((km >> b) & 1ull);
                acc |= rowbase[(size_t)b * NW + w] & m;
            }
            supp[w] |= acc;
        }
        __syncthreads();
    }
    for (int w = t; w < NW; w += 256) g_keepmask[w] = keepm[w];
}

// ---------------- K7: write output (N,5): boxes*keep, score*keep ----------------
__global__ void k_out(float* __restrict__ out) {
    int p = blockIdx.x * 256 + threadIdx.x;   // sorted position, exactly 9216
    int V = g_V;
    bool keep = (p < V) && ((g_keepmask[p >> 6] >> (p & 63)) & 1ull);
    int orig = g_order[p];
    float4 b = *(const float4*)&g_boxes[orig * 4];
    float s = g_scores[orig];
    float k = keep ? 1.0f : 0.0f;
    out[orig * 5 + 0] = b.x * k;
    out[orig * 5 + 1] = b.y * k;
    out[orig * 5 + 2] = b.z * k;
    out[orig * 5 + 3] = b.w * k;
    out[orig * 5 + 4] = s * k;
}

// ---------------- host launcher ----------------
extern "C" void kernel_launch(void* const* d_in, const int* in_sizes, int n_in,
                              void* d_out, int out_size) {
    const float* feat = (const float*)d_in[0];
    const float* w1   = (const float*)d_in[1];
    const float* b1   = (const float*)d_in[2];
    const float* w2   = (const float*)d_in[3];
    const float* b2   = (const float*)d_in[4];
    const float* w3   = (const float*)d_in[5];
    const float* b3   = (const float*)d_in[6];
    float* out = (float*)d_out;

    // 7 launches; 5th (k_mask) is the ncu-profiled one
    k_prep<<<TBLK + 9216 + 1, 256>>>(w1, feat);
    k_gemm<<<dim3(C_MID / 128, NPIX / 256, KSPLIT), 256>>>();
    k_heads<<<NPIX / 8, 256>>>(b1, w2, b2, w3, b3);
    k_rank<<<dim3(NBOX / 256, 9), 256>>>();
    k_mask<<<dim3(NW / 4, NW), 256>>>();
    k_nms<<<1, 256>>>();
    k_out<<<NBOX / 256, 256>>>(out);
}